// round 2
// baseline (speedup 1.0000x reference)
#include <cuda_runtime.h>
#include <cstdint>

// Problem constants
#define BB 2
#define SS 2048
#define DM 1024
#define HH 16
#define DH 64
#define NEG_MASK (-9e10f)

// ---------------- scratch (no allocation allowed) ----------------
__device__ float g_q[BB * HH * SS * DH];   // (B,H,S,Dh)
__device__ float g_k[BB * HH * SS * DH];
__device__ float g_v[BB * HH * SS * DH];
__device__ float g_ctx[BB * SS * DM];      // (B,S,D)

// ---------------------------------------------------------------
// NT GEMM: C[m,n] = sum_d A[m,d] * W[n,d] + bias[n]
// M=4096, N=1024, K=1024.  128x128 tile, BK=16, 256 threads, 8x8/thread.
// split==1: write into (B,H,S,Dh) head-split layout; else row-major MxN.
// ---------------------------------------------------------------
__global__ __launch_bounds__(256, 2) void gemm_nt_kernel(
    const float* __restrict__ A, const float* __restrict__ W,
    const float* __restrict__ bias, float* __restrict__ C,
    int M, int N, int Kd, int split)
{
    __shared__ float As[16][132];
    __shared__ float Ws[16][132];

    const int tid = threadIdx.x;
    const int tx = tid & 15;       // N dir
    const int ty = tid >> 4;       // M dir
    const int m0 = blockIdx.y * 128;
    const int n0 = blockIdx.x * 128;

    float acc[8][8];
#pragma unroll
    for (int i = 0; i < 8; i++)
#pragma unroll
        for (int j = 0; j < 8; j++) acc[i][j] = 0.f;

    const float* Ap = A + (size_t)m0 * Kd;
    const float* Wp = W + (size_t)n0 * Kd;

    for (int k0 = 0; k0 < Kd; k0 += 16) {
#pragma unroll
        for (int f = 0; f < 2; f++) {
            int idx = tid + f * 256;          // 0..511
            int r   = idx >> 2;               // 0..127
            int c4  = (idx & 3) * 4;          // 0,4,8,12
            float4 a = *(const float4*)(Ap + (size_t)r * Kd + k0 + c4);
            As[c4 + 0][r] = a.x; As[c4 + 1][r] = a.y;
            As[c4 + 2][r] = a.z; As[c4 + 3][r] = a.w;
            float4 w = *(const float4*)(Wp + (size_t)r * Kd + k0 + c4);
            Ws[c4 + 0][r] = w.x; Ws[c4 + 1][r] = w.y;
            Ws[c4 + 2][r] = w.z; Ws[c4 + 3][r] = w.w;
        }
        __syncthreads();

#pragma unroll
        for (int d = 0; d < 16; d++) {
            float4 a0 = *(const float4*)&As[d][ty * 8];
            float4 a1 = *(const float4*)&As[d][ty * 8 + 4];
            float4 b0 = *(const float4*)&Ws[d][tx * 8];
            float4 b1 = *(const float4*)&Ws[d][tx * 8 + 4];
            float ar[8] = {a0.x, a0.y, a0.z, a0.w, a1.x, a1.y, a1.z, a1.w};
            float br[8] = {b0.x, b0.y, b0.z, b0.w, b1.x, b1.y, b1.z, b1.w};
#pragma unroll
            for (int i = 0; i < 8; i++)
#pragma unroll
                for (int j = 0; j < 8; j++)
                    acc[i][j] += ar[i] * br[j];
        }
        __syncthreads();
    }

#pragma unroll
    for (int i = 0; i < 8; i++) {
        int mrow = m0 + ty * 8 + i;
#pragma unroll
        for (int j = 0; j < 8; j++) {
            int col = n0 + tx * 8 + j;
            float val = acc[i][j] + bias[col];
            if (split) {
                int b  = mrow >> 11;           // / 2048
                int sq = mrow & 2047;
                int h  = col >> 6;             // / 64
                int dh = col & 63;
                ((float*)C)[(((size_t)b * HH + h) * SS + sq) * DH + dh] = val;
            } else {
                C[(size_t)mrow * N + col] = val;
            }
        }
    }
}

// ---------------------------------------------------------------
// Flash attention: one CTA per (b, h, 64-row q-tile).
// 256 threads: ty=tid/16 -> 4 q-rows, tx=tid%16 -> 4 cols.
// Qt/Kt stored d-major (transposed) in smem; Vs row-major; P staged in Ps.
// Mask is read as 32-bit words (bool widened to int32/float32 by harness);
// "masked" iff word != 0 (works for both 0/1 int32 and 0.0/1.0 float32).
// ---------------------------------------------------------------
#define ATT_SMEM_FLOATS (4 * 64 * 68)

__global__ __launch_bounds__(256) void attn_kernel(
    const float* __restrict__ q, const float* __restrict__ k,
    const float* __restrict__ v, const uint32_t* __restrict__ mask,
    float* __restrict__ ctx)
{
    extern __shared__ float sm[];
    float (*Qt)[68] = (float(*)[68])sm;
    float (*Kt)[68] = (float(*)[68])(sm + 64 * 68);
    float (*Vs)[68] = (float(*)[68])(sm + 2 * 64 * 68);
    float (*Ps)[68] = (float(*)[68])(sm + 3 * 64 * 68);

    const int tid = threadIdx.x;
    const int tx = tid & 15;
    const int ty = tid >> 4;
    const int qt = blockIdx.x;
    const int h  = blockIdx.y;
    const int b  = blockIdx.z;
    const int qg0 = qt * 64;
    const float scale = 0.125f;  // 1/sqrt(64), exact power of 2

    const float* qptr  = q + (((size_t)b * HH + h) * SS + qg0) * DH;
    const float* kbase = k + (((size_t)b * HH + h) * SS) * DH;
    const float* vbase = v + (((size_t)b * HH + h) * SS) * DH;
    const uint32_t* mbase = mask + (size_t)b * SS * SS;

    // Load Q tile transposed (d-major), pre-scaled
#pragma unroll
    for (int rep = 0; rep < 4; rep++) {
        int r = rep * 16 + ty;
        int c = tx * 4;
        float4 vq = *(const float4*)(qptr + r * DH + c);
        Qt[c + 0][r] = vq.x * scale;
        Qt[c + 1][r] = vq.y * scale;
        Qt[c + 2][r] = vq.z * scale;
        Qt[c + 3][r] = vq.w * scale;
    }

    float mrow[4], lrow[4], o[4][4];
#pragma unroll
    for (int ii = 0; ii < 4; ii++) {
        mrow[ii] = -1e30f; lrow[ii] = 0.f;
#pragma unroll
        for (int e = 0; e < 4; e++) o[ii][e] = 0.f;
    }

    const int i0 = ty * 4;
    const int j0 = tx * 4;

    for (int kt = 0; kt < SS / 64; kt++) {
        const int kg0 = kt * 64;
        __syncthreads();  // prior PV done reading Vs/Ps before refill
        // Load K (transposed) and V tiles
#pragma unroll
        for (int rep = 0; rep < 4; rep++) {
            int r = rep * 16 + ty;
            int c = tx * 4;
            float4 vk = *(const float4*)(kbase + (size_t)(kg0 + r) * DH + c);
            Kt[c + 0][r] = vk.x; Kt[c + 1][r] = vk.y;
            Kt[c + 2][r] = vk.z; Kt[c + 3][r] = vk.w;
            *(float4*)&Vs[r][c] = *(const float4*)(vbase + (size_t)(kg0 + r) * DH + c);
        }
        __syncthreads();

        // S = Q K^T (4x4 per thread, d = 0..63)
        float s[4][4];
#pragma unroll
        for (int ii = 0; ii < 4; ii++)
#pragma unroll
            for (int jj = 0; jj < 4; jj++) s[ii][jj] = 0.f;

#pragma unroll 16
        for (int d = 0; d < 64; d++) {
            float4 a  = *(const float4*)&Qt[d][i0];
            float4 bb = *(const float4*)&Kt[d][j0];
            s[0][0] += a.x * bb.x; s[0][1] += a.x * bb.y; s[0][2] += a.x * bb.z; s[0][3] += a.x * bb.w;
            s[1][0] += a.y * bb.x; s[1][1] += a.y * bb.y; s[1][2] += a.y * bb.z; s[1][3] += a.y * bb.w;
            s[2][0] += a.z * bb.x; s[2][1] += a.z * bb.y; s[2][2] += a.z * bb.z; s[2][3] += a.z * bb.w;
            s[3][0] += a.w * bb.x; s[3][1] += a.w * bb.y; s[3][2] += a.w * bb.z; s[3][3] += a.w * bb.w;
        }

        // mask + online softmax per row
#pragma unroll
        for (int ii = 0; ii < 4; ii++) {
            int qi = qg0 + i0 + ii;
            uint4 mk = *(const uint4*)(mbase + (size_t)qi * SS + kg0 + j0);
            if (mk.x) s[ii][0] += NEG_MASK;
            if (mk.y) s[ii][1] += NEG_MASK;
            if (mk.z) s[ii][2] += NEG_MASK;
            if (mk.w) s[ii][3] += NEG_MASK;

            float rmax = fmaxf(fmaxf(s[ii][0], s[ii][1]), fmaxf(s[ii][2], s[ii][3]));
#pragma unroll
            for (int off = 8; off >= 1; off >>= 1)
                rmax = fmaxf(rmax, __shfl_xor_sync(0xffffffffu, rmax, off));

            float mnew  = fmaxf(mrow[ii], rmax);
            float alpha = __expf(mrow[ii] - mnew);
            float p0 = __expf(s[ii][0] - mnew);
            float p1 = __expf(s[ii][1] - mnew);
            float p2 = __expf(s[ii][2] - mnew);
            float p3 = __expf(s[ii][3] - mnew);
            float rs = p0 + p1 + p2 + p3;
#pragma unroll
            for (int off = 8; off >= 1; off >>= 1)
                rs += __shfl_xor_sync(0xffffffffu, rs, off);

            lrow[ii] = lrow[ii] * alpha + rs;
            mrow[ii] = mnew;
            o[ii][0] *= alpha; o[ii][1] *= alpha; o[ii][2] *= alpha; o[ii][3] *= alpha;

            float4 pv4 = make_float4(p0, p1, p2, p3);
            *(float4*)&Ps[i0 + ii][j0] = pv4;
        }
        __syncthreads();

        // O += P V  (j = 0..63, unrolled by 4)
#pragma unroll 8
        for (int j = 0; j < 64; j += 4) {
            float4 v0 = *(const float4*)&Vs[j + 0][j0];
            float4 v1 = *(const float4*)&Vs[j + 1][j0];
            float4 v2 = *(const float4*)&Vs[j + 2][j0];
            float4 v3 = *(const float4*)&Vs[j + 3][j0];
#pragma unroll
            for (int ii = 0; ii < 4; ii++) {
                float4 p = *(const float4*)&Ps[i0 + ii][j];
                o[ii][0] += p.x * v0.x + p.y * v1.x + p.z * v2.x + p.w * v3.x;
                o[ii][1] += p.x * v0.y + p.y * v1.y + p.z * v2.y + p.w * v3.y;
                o[ii][2] += p.x * v0.z + p.y * v1.z + p.z * v2.z + p.w * v3.z;
                o[ii][3] += p.x * v0.w + p.y * v1.w + p.z * v2.w + p.w * v3.w;
            }
        }
    }

    // epilogue: normalize, write ctx in (B,S,D) layout
#pragma unroll
    for (int ii = 0; ii < 4; ii++) {
        float inv = 1.f / lrow[ii];
        int qi = qg0 + i0 + ii;
        float4 r;
        r.x = o[ii][0] * inv; r.y = o[ii][1] * inv;
        r.z = o[ii][2] * inv; r.w = o[ii][3] * inv;
        *(float4*)(ctx + ((size_t)b * SS + qi) * DM + h * DH + j0) = r;
    }
}

// ---------------------------------------------------------------
extern "C" void kernel_launch(void* const* d_in, const int* in_sizes, int n_in,
                              void* d_out, int out_size)
{
    const float* Q  = (const float*)d_in[0];
    const float* K  = (const float*)d_in[1];
    const float* V  = (const float*)d_in[2];
    const uint32_t* mask = (const uint32_t*)d_in[3];
    const float* Wq = (const float*)d_in[4];
    const float* bq = (const float*)d_in[5];
    const float* Wk = (const float*)d_in[6];
    const float* bk = (const float*)d_in[7];
    const float* Wv = (const float*)d_in[8];
    const float* bv = (const float*)d_in[9];
    const float* Wo = (const float*)d_in[10];
    const float* bo = (const float*)d_in[11];
    float* out = (float*)d_out;

    float *qb, *kb, *vb, *ctx;
    cudaGetSymbolAddress((void**)&qb,  g_q);
    cudaGetSymbolAddress((void**)&kb,  g_k);
    cudaGetSymbolAddress((void**)&vb,  g_v);
    cudaGetSymbolAddress((void**)&ctx, g_ctx);

    const int M = BB * SS;          // 4096
    dim3 gg(DM / 128, M / 128);     // (8, 32)
    dim3 tt(256);

    gemm_nt_kernel<<<gg, tt>>>(Q, Wq, bq, qb, M, DM, DM, 1);
    gemm_nt_kernel<<<gg, tt>>>(K, Wk, bk, kb, M, DM, DM, 1);
    gemm_nt_kernel<<<gg, tt>>>(V, Wv, bv, vb, M, DM, DM, 1);

    const int smem = ATT_SMEM_FLOATS * (int)sizeof(float);  // 69,632 B
    cudaFuncSetAttribute(attn_kernel, cudaFuncAttributeMaxDynamicSharedMemorySize, smem);
    attn_kernel<<<dim3(SS / 64, HH, BB), tt, smem>>>(qb, kb, vb, mask, ctx);

    gemm_nt_kernel<<<gg, tt>>>(ctx, Wo, bo, out, M, DM, DM, 0);
}

// round 6
// speedup vs baseline: 2.0842x; 2.0842x over previous
#include <cuda_runtime.h>
#include <cstdint>

// Problem constants
#define BB 2
#define SS 2048
#define DM 1024
#define HH 16
#define DH 64
#define NEG_MASK (-9e10f)

// ---------------- scratch (no allocation allowed) ----------------
__device__ float g_q[BB * HH * SS * DH];   // (B,H,S,Dh)
__device__ float g_k[BB * HH * SS * DH];
__device__ float g_v[BB * HH * SS * DH];
__device__ float g_ctx[BB * SS * DM];      // (B,S,D)

// ---------------- tf32 helpers ----------------
__device__ __forceinline__ uint32_t f2tf(float x) {
    uint32_t r;
    asm volatile("cvt.rna.tf32.f32 %0, %1;" : "=r"(r) : "f"(x));
    return r;
}

__device__ __forceinline__ void mma8(float* d, const uint32_t* a, uint32_t b0, uint32_t b1) {
    asm volatile(
        "mma.sync.aligned.m16n8k8.row.col.f32.tf32.tf32.f32 "
        "{%0,%1,%2,%3}, {%4,%5,%6,%7}, {%8,%9}, {%0,%1,%2,%3};\n"
        : "+f"(d[0]), "+f"(d[1]), "+f"(d[2]), "+f"(d[3])
        : "r"(a[0]), "r"(a[1]), "r"(a[2]), "r"(a[3]), "r"(b0), "r"(b1));
}

// ---------------------------------------------------------------
// NT GEMM (tf32 tensor cores): C[m,n] = sum_d A[m,d]*W[n,d] + bias[n]
// M=4096, N=1024, K=1024. Tile 128x128, BK=32, 256 threads (8 warps).
// Warp tile 64x32 (warp_m = warp&1, warp_n = warp>>1).
// split==1: write (B,H,S,Dh) head-split layout; else row-major MxN.
// ---------------------------------------------------------------
#define GBK 32
#define GPAD 36   // (36%32)=4 -> frag addr (4g+t)%32 conflict-free

__global__ __launch_bounds__(256, 1) void gemm_tc_kernel(
    const float* __restrict__ A, const float* __restrict__ W,
    const float* __restrict__ bias, float* __restrict__ C, int split)
{
    __shared__ uint32_t As[128 * GPAD];
    __shared__ uint32_t Ws[128 * GPAD];

    const int tid  = threadIdx.x;
    const int warp = tid >> 5;
    const int lane = tid & 31;
    const int g    = lane >> 2;
    const int t4   = lane & 3;
    const int wm   = warp & 1;      // 0..1
    const int wn   = warp >> 1;     // 0..3
    const int m0   = blockIdx.y * 128;
    const int n0   = blockIdx.x * 128;

    float acc[4][4][4];
#pragma unroll
    for (int mt = 0; mt < 4; mt++)
#pragma unroll
        for (int nt = 0; nt < 4; nt++)
#pragma unroll
            for (int r = 0; r < 4; r++) acc[mt][nt][r] = 0.f;

    const float* Ap = A + (size_t)m0 * DM;
    const float* Wp = W + (size_t)n0 * DM;

    for (int k0 = 0; k0 < DM; k0 += GBK) {
        // cooperative load + tf32 convert: 128x32 each
#pragma unroll
        for (int i = 0; i < 4; i++) {
            int idx = tid + i * 256;       // 0..1023
            int r   = idx >> 3;            // 0..127
            int c4  = (idx & 7) * 4;       // 0..28
            float4 a = *(const float4*)(Ap + (size_t)r * DM + k0 + c4);
            As[r * GPAD + c4 + 0] = f2tf(a.x);
            As[r * GPAD + c4 + 1] = f2tf(a.y);
            As[r * GPAD + c4 + 2] = f2tf(a.z);
            As[r * GPAD + c4 + 3] = f2tf(a.w);
            float4 w = *(const float4*)(Wp + (size_t)r * DM + k0 + c4);
            Ws[r * GPAD + c4 + 0] = f2tf(w.x);
            Ws[r * GPAD + c4 + 1] = f2tf(w.y);
            Ws[r * GPAD + c4 + 2] = f2tf(w.z);
            Ws[r * GPAD + c4 + 3] = f2tf(w.w);
        }
        __syncthreads();

#pragma unroll
        for (int ks = 0; ks < GBK / 8; ks++) {
            const int kc = ks * 8 + t4;
            uint32_t af[4][4];
#pragma unroll
            for (int mt = 0; mt < 4; mt++) {
                int row = wm * 64 + mt * 16 + g;
                af[mt][0] = As[row * GPAD + kc];
                af[mt][1] = As[(row + 8) * GPAD + kc];
                af[mt][2] = As[row * GPAD + kc + 4];
                af[mt][3] = As[(row + 8) * GPAD + kc + 4];
            }
#pragma unroll
            for (int nt = 0; nt < 4; nt++) {
                int col = wn * 32 + nt * 8 + g;
                uint32_t b0 = Ws[col * GPAD + kc];
                uint32_t b1 = Ws[col * GPAD + kc + 4];
#pragma unroll
                for (int mt = 0; mt < 4; mt++)
                    mma8(acc[mt][nt], af[mt], b0, b1);
            }
        }
        __syncthreads();
    }

    // epilogue
#pragma unroll
    for (int mt = 0; mt < 4; mt++) {
        int r0 = m0 + wm * 64 + mt * 16 + g;
        int r1 = r0 + 8;
#pragma unroll
        for (int nt = 0; nt < 4; nt++) {
            int c = n0 + wn * 32 + nt * 8 + 2 * t4;
            float2 bi = *(const float2*)(bias + c);
            float v00 = acc[mt][nt][0] + bi.x;
            float v01 = acc[mt][nt][1] + bi.y;
            float v10 = acc[mt][nt][2] + bi.x;
            float v11 = acc[mt][nt][3] + bi.y;
            if (split) {
                int h  = c >> 6;
                int dh = c & 63;
                int b0i = r0 >> 11, s0 = r0 & 2047;
                int b1i = r1 >> 11, s1 = r1 & 2047;
                float* p0 = (float*)C + (((size_t)b0i * HH + h) * SS + s0) * DH + dh;
                float* p1 = (float*)C + (((size_t)b1i * HH + h) * SS + s1) * DH + dh;
                p0[0] = v00; p0[1] = v01;
                p1[0] = v10; p1[1] = v11;
            } else {
                *(float2*)(C + (size_t)r0 * DM + c) = make_float2(v00, v01);
                *(float2*)(C + (size_t)r1 * DM + c) = make_float2(v10, v11);
            }
        }
    }
}

// ---------------------------------------------------------------
// Flash attention (tf32 tensor cores).
// CTA: 128 q-rows, loop K in 64-col chunks. 8 warps, each owns 16 q-rows
// (full 64-col width) -> softmax entirely warp-local.
// Q/K/V/P staged in smem as tf32; P round-trips via smem for PV mma.
// ---------------------------------------------------------------
#define QT 128
#define KT 64
#define QP 68
#define KP 68
#define VP 68
#define PP 76
#define ATT_SMEM_U32 (QT * QP + KT * KP + KT * VP + QT * PP)

__global__ __launch_bounds__(256) void attn_tc_kernel(
    const float* __restrict__ q, const float* __restrict__ k,
    const float* __restrict__ v, const uint32_t* __restrict__ mask,
    float* __restrict__ ctx)
{
    extern __shared__ uint32_t su[];
    uint32_t* Qs = su;                    // [128][68]
    uint32_t* Ks = Qs + QT * QP;          // [64][68]
    uint32_t* Vs = Ks + KT * KP;          // [64][68]
    uint32_t* Ps = Vs + KT * VP;          // [128][76]

    const int tid  = threadIdx.x;
    const int warp = tid >> 5;
    const int lane = tid & 31;
    const int g    = lane >> 2;
    const int t4   = lane & 3;
    const int qt   = blockIdx.x;
    const int h    = blockIdx.y;
    const int b    = blockIdx.z;
    const int qg0  = qt * QT;
    const int wrow0 = warp * 16;

    const float* qptr  = q + (((size_t)b * HH + h) * SS + qg0) * DH;
    const float* kbase = k + (((size_t)b * HH + h) * SS) * DH;
    const float* vbase = v + (((size_t)b * HH + h) * SS) * DH;
    const uint32_t* mbase = mask + (size_t)b * SS * SS;

    // Load Q tile (pre-scaled by 1/8, tf32)
#pragma unroll
    for (int i = 0; i < 8; i++) {
        int idx = tid + i * 256;     // 0..2047
        int r   = idx >> 4;          // 0..127
        int c4  = (idx & 15) * 4;    // 0..60
        float4 a = *(const float4*)(qptr + (size_t)r * DH + c4);
        Qs[r * QP + c4 + 0] = f2tf(a.x * 0.125f);
        Qs[r * QP + c4 + 1] = f2tf(a.y * 0.125f);
        Qs[r * QP + c4 + 2] = f2tf(a.z * 0.125f);
        Qs[r * QP + c4 + 3] = f2tf(a.w * 0.125f);
    }

    float o[8][4];
#pragma unroll
    for (int nt = 0; nt < 8; nt++)
#pragma unroll
        for (int r = 0; r < 4; r++) o[nt][r] = 0.f;
    float mr0 = -1e30f, mr1 = -1e30f, l0 = 0.f, l1 = 0.f;

    const int r0g = qg0 + wrow0 + g;       // global q row (g)
    const int r1g = r0g + 8;               // global q row (g+8)
    const uint32_t* mrow0p = mbase + (size_t)r0g * SS;
    const uint32_t* mrow1p = mbase + (size_t)r1g * SS;

    for (int kt = 0; kt < SS / KT; kt++) {
        const int kg0 = kt * KT;
        __syncthreads();
        // load K,V chunk (64x64 each), tf32
#pragma unroll
        for (int i = 0; i < 4; i++) {
            int idx = tid + i * 256;   // 0..1023
            int r   = idx >> 4;        // 0..63
            int c4  = (idx & 15) * 4;
            float4 kv = *(const float4*)(kbase + (size_t)(kg0 + r) * DH + c4);
            Ks[r * KP + c4 + 0] = f2tf(kv.x);
            Ks[r * KP + c4 + 1] = f2tf(kv.y);
            Ks[r * KP + c4 + 2] = f2tf(kv.z);
            Ks[r * KP + c4 + 3] = f2tf(kv.w);
            float4 vv = *(const float4*)(vbase + (size_t)(kg0 + r) * DH + c4);
            Vs[r * VP + c4 + 0] = f2tf(vv.x);
            Vs[r * VP + c4 + 1] = f2tf(vv.y);
            Vs[r * VP + c4 + 2] = f2tf(vv.z);
            Vs[r * VP + c4 + 3] = f2tf(vv.w);
        }
        __syncthreads();

        // ---- S = Q K^T : 16 rows x 64 cols per warp ----
        float s[8][4];
#pragma unroll
        for (int nt = 0; nt < 8; nt++)
#pragma unroll
            for (int r = 0; r < 4; r++) s[nt][r] = 0.f;

#pragma unroll
        for (int ks = 0; ks < 8; ks++) {
            const int kc = ks * 8 + t4;
            uint32_t af[4];
            af[0] = Qs[(wrow0 + g) * QP + kc];
            af[1] = Qs[(wrow0 + 8 + g) * QP + kc];
            af[2] = Qs[(wrow0 + g) * QP + kc + 4];
            af[3] = Qs[(wrow0 + 8 + g) * QP + kc + 4];
#pragma unroll
            for (int nt = 0; nt < 8; nt++) {
                uint32_t b0 = Ks[(nt * 8 + g) * KP + kc];
                uint32_t b1 = Ks[(nt * 8 + g) * KP + kc + 4];
                mma8(s[nt], af, b0, b1);
            }
        }

        // ---- mask + online softmax (rows r0g, r1g) ----
        float M0 = -1e30f, M1 = -1e30f;
#pragma unroll
        for (int nt = 0; nt < 8; nt++) {
            int c = kg0 + nt * 8 + 2 * t4;
            uint2 mk0 = *(const uint2*)(mrow0p + c);
            uint2 mk1 = *(const uint2*)(mrow1p + c);
            if (mk0.x) s[nt][0] += NEG_MASK;
            if (mk0.y) s[nt][1] += NEG_MASK;
            if (mk1.x) s[nt][2] += NEG_MASK;
            if (mk1.y) s[nt][3] += NEG_MASK;
            M0 = fmaxf(M0, fmaxf(s[nt][0], s[nt][1]));
            M1 = fmaxf(M1, fmaxf(s[nt][2], s[nt][3]));
        }
        M0 = fmaxf(M0, __shfl_xor_sync(0xffffffffu, M0, 1));
        M0 = fmaxf(M0, __shfl_xor_sync(0xffffffffu, M0, 2));
        M1 = fmaxf(M1, __shfl_xor_sync(0xffffffffu, M1, 1));
        M1 = fmaxf(M1, __shfl_xor_sync(0xffffffffu, M1, 2));

        float mn0 = fmaxf(mr0, M0);
        float mn1 = fmaxf(mr1, M1);
        float a0 = __expf(mr0 - mn0);
        float a1 = __expf(mr1 - mn1);
        mr0 = mn0; mr1 = mn1;

        __syncwarp();   // prior PV reads of Ps done before overwrite
        float sum0 = 0.f, sum1 = 0.f;
#pragma unroll
        for (int nt = 0; nt < 8; nt++) {
            float p00 = __expf(s[nt][0] - mn0);
            float p01 = __expf(s[nt][1] - mn0);
            float p10 = __expf(s[nt][2] - mn1);
            float p11 = __expf(s[nt][3] - mn1);
            sum0 += p00 + p01;
            sum1 += p10 + p11;
            int c = nt * 8 + 2 * t4;
            Ps[(wrow0 + g) * PP + c]     = f2tf(p00);
            Ps[(wrow0 + g) * PP + c + 1] = f2tf(p01);
            Ps[(wrow0 + 8 + g) * PP + c]     = f2tf(p10);
            Ps[(wrow0 + 8 + g) * PP + c + 1] = f2tf(p11);
        }
        sum0 += __shfl_xor_sync(0xffffffffu, sum0, 1);
        sum0 += __shfl_xor_sync(0xffffffffu, sum0, 2);
        sum1 += __shfl_xor_sync(0xffffffffu, sum1, 1);
        sum1 += __shfl_xor_sync(0xffffffffu, sum1, 2);
        l0 = l0 * a0 + sum0;
        l1 = l1 * a1 + sum1;

#pragma unroll
        for (int nt = 0; nt < 8; nt++) {
            o[nt][0] *= a0; o[nt][1] *= a0;
            o[nt][2] *= a1; o[nt][3] *= a1;
        }
        __syncwarp();   // P visible to all lanes of this warp

        // ---- O += P V ----
#pragma unroll
        for (int ks = 0; ks < 8; ks++) {
            const int kc = ks * 8;
            uint32_t af[4];
            af[0] = Ps[(wrow0 + g) * PP + kc + t4];
            af[1] = Ps[(wrow0 + 8 + g) * PP + kc + t4];
            af[2] = Ps[(wrow0 + g) * PP + kc + t4 + 4];
            af[3] = Ps[(wrow0 + 8 + g) * PP + kc + t4 + 4];
#pragma unroll
            for (int nt = 0; nt < 8; nt++) {
                uint32_t b0 = Vs[(kc + t4) * VP + nt * 8 + g];
                uint32_t b1 = Vs[(kc + t4 + 4) * VP + nt * 8 + g];
                mma8(o[nt], af, b0, b1);
            }
        }
    }

    // ---- epilogue: normalize, write ctx (B,S,D) ----
    float inv0 = 1.f / l0, inv1 = 1.f / l1;
    float* out0 = ctx + ((size_t)b * SS + r0g) * DM + h * DH;
    float* out1 = ctx + ((size_t)b * SS + r1g) * DM + h * DH;
#pragma unroll
    for (int nt = 0; nt < 8; nt++) {
        int c = nt * 8 + 2 * t4;
        *(float2*)(out0 + c) = make_float2(o[nt][0] * inv0, o[nt][1] * inv0);
        *(float2*)(out1 + c) = make_float2(o[nt][2] * inv1, o[nt][3] * inv1);
    }
}

// ---------------------------------------------------------------
extern "C" void kernel_launch(void* const* d_in, const int* in_sizes, int n_in,
                              void* d_out, int out_size)
{
    const float* Q  = (const float*)d_in[0];
    const float* K  = (const float*)d_in[1];
    const float* V  = (const float*)d_in[2];
    const uint32_t* mask = (const uint32_t*)d_in[3];
    const float* Wq = (const float*)d_in[4];
    const float* bq = (const float*)d_in[5];
    const float* Wk = (const float*)d_in[6];
    const float* bk = (const float*)d_in[7];
    const float* Wv = (const float*)d_in[8];
    const float* bv = (const float*)d_in[9];
    const float* Wo = (const float*)d_in[10];
    const float* bo = (const float*)d_in[11];
    float* out = (float*)d_out;

    float *qb, *kb, *vb, *ctx;
    cudaGetSymbolAddress((void**)&qb,  g_q);
    cudaGetSymbolAddress((void**)&kb,  g_k);
    cudaGetSymbolAddress((void**)&vb,  g_v);
    cudaGetSymbolAddress((void**)&ctx, g_ctx);

    dim3 gg(DM / 128, (BB * SS) / 128);   // (8, 32)
    dim3 tt(256);

    gemm_tc_kernel<<<gg, tt>>>(Q, Wq, bq, qb, 1);
    gemm_tc_kernel<<<gg, tt>>>(K, Wk, bk, kb, 1);
    gemm_tc_kernel<<<gg, tt>>>(V, Wv, bv, vb, 1);

    const int smem = ATT_SMEM_U32 * (int)sizeof(uint32_t);  // ~108.5 KB
    cudaFuncSetAttribute(attn_tc_kernel, cudaFuncAttributeMaxDynamicSharedMemorySize, smem);
    attn_tc_kernel<<<dim3(SS / QT, HH, BB), tt, smem>>>(qb, kb, vb, mask, ctx);

    gemm_tc_kernel<<<gg, tt>>>(ctx, Wo, bo, out, 0);
}

// round 7
// speedup vs baseline: 2.0866x; 1.0011x over previous
#include <cuda_runtime.h>
#include <cstdint>

// Problem constants
#define BB 2
#define SS 2048
#define DM 1024
#define HH 16
#define DH 64
#define NEG_MASK (-9e10f)

// ---------------- scratch (no allocation allowed) ----------------
__device__ float g_q[BB * HH * SS * DH];   // (B,H,S,Dh)
__device__ float g_k[BB * HH * SS * DH];
__device__ float g_v[BB * HH * SS * DH];
__device__ float g_ctx[BB * SS * DM];      // (B,S,D)

// ---------------- tf32 helpers ----------------
__device__ __forceinline__ uint32_t f2tf(float x) {
    uint32_t r;
    asm volatile("cvt.rna.tf32.f32 %0, %1;" : "=r"(r) : "f"(x));
    return r;
}

__device__ __forceinline__ void mma8(float* d, const uint32_t* a, uint32_t b0, uint32_t b1) {
    asm volatile(
        "mma.sync.aligned.m16n8k8.row.col.f32.tf32.tf32.f32 "
        "{%0,%1,%2,%3}, {%4,%5,%6,%7}, {%8,%9}, {%0,%1,%2,%3};\n"
        : "+f"(d[0]), "+f"(d[1]), "+f"(d[2]), "+f"(d[3])
        : "r"(a[0]), "r"(a[1]), "r"(a[2]), "r"(a[3]), "r"(b0), "r"(b1));
}

// ---------------------------------------------------------------
// NT GEMM (tf32 tensor cores): C[m,n] = sum_d A[m,d]*W[n,d] + bias[n]
// M=4096, N=1024, K=1024. Tile 128x128, BK=32, 256 threads (8 warps).
// Warp tile 64x32 (warp_m = warp&1, warp_n = warp>>1).
// split==1: write (B,H,S,Dh) head-split layout; else row-major MxN.
// ---------------------------------------------------------------
#define GBK 32
#define GPAD 36   // (36%32)=4 -> frag addr (4g+t)%32 conflict-free

__global__ __launch_bounds__(256, 1) void gemm_tc_kernel(
    const float* __restrict__ A, const float* __restrict__ W,
    const float* __restrict__ bias, float* __restrict__ C, int split)
{
    __shared__ uint32_t As[128 * GPAD];
    __shared__ uint32_t Ws[128 * GPAD];

    const int tid  = threadIdx.x;
    const int warp = tid >> 5;
    const int lane = tid & 31;
    const int g    = lane >> 2;
    const int t4   = lane & 3;
    const int wm   = warp & 1;      // 0..1
    const int wn   = warp >> 1;     // 0..3
    const int m0   = blockIdx.y * 128;
    const int n0   = blockIdx.x * 128;

    float acc[4][4][4];
#pragma unroll
    for (int mt = 0; mt < 4; mt++)
#pragma unroll
        for (int nt = 0; nt < 4; nt++)
#pragma unroll
            for (int r = 0; r < 4; r++) acc[mt][nt][r] = 0.f;

    const float* Ap = A + (size_t)m0 * DM;
    const float* Wp = W + (size_t)n0 * DM;

    for (int k0 = 0; k0 < DM; k0 += GBK) {
        // cooperative load + tf32 convert: 128x32 each
#pragma unroll
        for (int i = 0; i < 4; i++) {
            int idx = tid + i * 256;       // 0..1023
            int r   = idx >> 3;            // 0..127
            int c4  = (idx & 7) * 4;       // 0..28
            float4 a = *(const float4*)(Ap + (size_t)r * DM + k0 + c4);
            As[r * GPAD + c4 + 0] = f2tf(a.x);
            As[r * GPAD + c4 + 1] = f2tf(a.y);
            As[r * GPAD + c4 + 2] = f2tf(a.z);
            As[r * GPAD + c4 + 3] = f2tf(a.w);
            float4 w = *(const float4*)(Wp + (size_t)r * DM + k0 + c4);
            Ws[r * GPAD + c4 + 0] = f2tf(w.x);
            Ws[r * GPAD + c4 + 1] = f2tf(w.y);
            Ws[r * GPAD + c4 + 2] = f2tf(w.z);
            Ws[r * GPAD + c4 + 3] = f2tf(w.w);
        }
        __syncthreads();

#pragma unroll
        for (int ks = 0; ks < GBK / 8; ks++) {
            const int kc = ks * 8 + t4;
            uint32_t af[4][4];
#pragma unroll
            for (int mt = 0; mt < 4; mt++) {
                int row = wm * 64 + mt * 16 + g;
                af[mt][0] = As[row * GPAD + kc];
                af[mt][1] = As[(row + 8) * GPAD + kc];
                af[mt][2] = As[row * GPAD + kc + 4];
                af[mt][3] = As[(row + 8) * GPAD + kc + 4];
            }
#pragma unroll
            for (int nt = 0; nt < 4; nt++) {
                int col = wn * 32 + nt * 8 + g;
                uint32_t b0 = Ws[col * GPAD + kc];
                uint32_t b1 = Ws[col * GPAD + kc + 4];
#pragma unroll
                for (int mt = 0; mt < 4; mt++)
                    mma8(acc[mt][nt], af[mt], b0, b1);
            }
        }
        __syncthreads();
    }

    // epilogue
#pragma unroll
    for (int mt = 0; mt < 4; mt++) {
        int r0 = m0 + wm * 64 + mt * 16 + g;
        int r1 = r0 + 8;
#pragma unroll
        for (int nt = 0; nt < 4; nt++) {
            int c = n0 + wn * 32 + nt * 8 + 2 * t4;
            float2 bi = *(const float2*)(bias + c);
            float v00 = acc[mt][nt][0] + bi.x;
            float v01 = acc[mt][nt][1] + bi.y;
            float v10 = acc[mt][nt][2] + bi.x;
            float v11 = acc[mt][nt][3] + bi.y;
            if (split) {
                int h  = c >> 6;
                int dh = c & 63;
                int b0i = r0 >> 11, s0 = r0 & 2047;
                int b1i = r1 >> 11, s1 = r1 & 2047;
                float* p0 = (float*)C + (((size_t)b0i * HH + h) * SS + s0) * DH + dh;
                float* p1 = (float*)C + (((size_t)b1i * HH + h) * SS + s1) * DH + dh;
                p0[0] = v00; p0[1] = v01;
                p1[0] = v10; p1[1] = v11;
            } else {
                *(float2*)(C + (size_t)r0 * DM + c) = make_float2(v00, v01);
                *(float2*)(C + (size_t)r1 * DM + c) = make_float2(v10, v11);
            }
        }
    }
}

// ---------------------------------------------------------------
// Flash attention (tf32 tensor cores).
// CTA: 128 q-rows, loop K in 64-col chunks. 8 warps, each owns 16 q-rows
// (full 64-col width) -> softmax entirely warp-local.
// Q/K/V/P staged in smem as tf32; P round-trips via smem for PV mma.
// ---------------------------------------------------------------
#define QT 128
#define KT 64
#define QP 68
#define KP 68
#define VP 68
#define PP 76
#define ATT_SMEM_U32 (QT * QP + KT * KP + KT * VP + QT * PP)

__global__ __launch_bounds__(256) void attn_tc_kernel(
    const float* __restrict__ q, const float* __restrict__ k,
    const float* __restrict__ v, const uint32_t* __restrict__ mask,
    float* __restrict__ ctx)
{
    extern __shared__ uint32_t su[];
    uint32_t* Qs = su;                    // [128][68]
    uint32_t* Ks = Qs + QT * QP;          // [64][68]
    uint32_t* Vs = Ks + KT * KP;          // [64][68]
    uint32_t* Ps = Vs + KT * VP;          // [128][76]

    const int tid  = threadIdx.x;
    const int warp = tid >> 5;
    const int lane = tid & 31;
    const int g    = lane >> 2;
    const int t4   = lane & 3;
    const int qt   = blockIdx.x;
    const int h    = blockIdx.y;
    const int b    = blockIdx.z;
    const int qg0  = qt * QT;
    const int wrow0 = warp * 16;

    const float* qptr  = q + (((size_t)b * HH + h) * SS + qg0) * DH;
    const float* kbase = k + (((size_t)b * HH + h) * SS) * DH;
    const float* vbase = v + (((size_t)b * HH + h) * SS) * DH;
    const uint32_t* mbase = mask + (size_t)b * SS * SS;

    // Load Q tile (pre-scaled by 1/8, tf32)
#pragma unroll
    for (int i = 0; i < 8; i++) {
        int idx = tid + i * 256;     // 0..2047
        int r   = idx >> 4;          // 0..127
        int c4  = (idx & 15) * 4;    // 0..60
        float4 a = *(const float4*)(qptr + (size_t)r * DH + c4);
        Qs[r * QP + c4 + 0] = f2tf(a.x * 0.125f);
        Qs[r * QP + c4 + 1] = f2tf(a.y * 0.125f);
        Qs[r * QP + c4 + 2] = f2tf(a.z * 0.125f);
        Qs[r * QP + c4 + 3] = f2tf(a.w * 0.125f);
    }

    float o[8][4];
#pragma unroll
    for (int nt = 0; nt < 8; nt++)
#pragma unroll
        for (int r = 0; r < 4; r++) o[nt][r] = 0.f;
    float mr0 = -1e30f, mr1 = -1e30f, l0 = 0.f, l1 = 0.f;

    const int r0g = qg0 + wrow0 + g;       // global q row (g)
    const int r1g = r0g + 8;               // global q row (g+8)
    const uint32_t* mrow0p = mbase + (size_t)r0g * SS;
    const uint32_t* mrow1p = mbase + (size_t)r1g * SS;

    for (int kt = 0; kt < SS / KT; kt++) {
        const int kg0 = kt * KT;
        __syncthreads();
        // load K,V chunk (64x64 each), tf32
#pragma unroll
        for (int i = 0; i < 4; i++) {
            int idx = tid + i * 256;   // 0..1023
            int r   = idx >> 4;        // 0..63
            int c4  = (idx & 15) * 4;
            float4 kv = *(const float4*)(kbase + (size_t)(kg0 + r) * DH + c4);
            Ks[r * KP + c4 + 0] = f2tf(kv.x);
            Ks[r * KP + c4 + 1] = f2tf(kv.y);
            Ks[r * KP + c4 + 2] = f2tf(kv.z);
            Ks[r * KP + c4 + 3] = f2tf(kv.w);
            float4 vv = *(const float4*)(vbase + (size_t)(kg0 + r) * DH + c4);
            Vs[r * VP + c4 + 0] = f2tf(vv.x);
            Vs[r * VP + c4 + 1] = f2tf(vv.y);
            Vs[r * VP + c4 + 2] = f2tf(vv.z);
            Vs[r * VP + c4 + 3] = f2tf(vv.w);
        }
        __syncthreads();

        // ---- S = Q K^T : 16 rows x 64 cols per warp ----
        float s[8][4];
#pragma unroll
        for (int nt = 0; nt < 8; nt++)
#pragma unroll
            for (int r = 0; r < 4; r++) s[nt][r] = 0.f;

#pragma unroll
        for (int ks = 0; ks < 8; ks++) {
            const int kc = ks * 8 + t4;
            uint32_t af[4];
            af[0] = Qs[(wrow0 + g) * QP + kc];
            af[1] = Qs[(wrow0 + 8 + g) * QP + kc];
            af[2] = Qs[(wrow0 + g) * QP + kc + 4];
            af[3] = Qs[(wrow0 + 8 + g) * QP + kc + 4];
#pragma unroll
            for (int nt = 0; nt < 8; nt++) {
                uint32_t b0 = Ks[(nt * 8 + g) * KP + kc];
                uint32_t b1 = Ks[(nt * 8 + g) * KP + kc + 4];
                mma8(s[nt], af, b0, b1);
            }
        }

        // ---- mask + online softmax (rows r0g, r1g) ----
        float M0 = -1e30f, M1 = -1e30f;
#pragma unroll
        for (int nt = 0; nt < 8; nt++) {
            int c = kg0 + nt * 8 + 2 * t4;
            uint2 mk0 = *(const uint2*)(mrow0p + c);
            uint2 mk1 = *(const uint2*)(mrow1p + c);
            if (mk0.x) s[nt][0] += NEG_MASK;
            if (mk0.y) s[nt][1] += NEG_MASK;
            if (mk1.x) s[nt][2] += NEG_MASK;
            if (mk1.y) s[nt][3] += NEG_MASK;
            M0 = fmaxf(M0, fmaxf(s[nt][0], s[nt][1]));
            M1 = fmaxf(M1, fmaxf(s[nt][2], s[nt][3]));
        }
        M0 = fmaxf(M0, __shfl_xor_sync(0xffffffffu, M0, 1));
        M0 = fmaxf(M0, __shfl_xor_sync(0xffffffffu, M0, 2));
        M1 = fmaxf(M1, __shfl_xor_sync(0xffffffffu, M1, 1));
        M1 = fmaxf(M1, __shfl_xor_sync(0xffffffffu, M1, 2));

        float mn0 = fmaxf(mr0, M0);
        float mn1 = fmaxf(mr1, M1);
        float a0 = __expf(mr0 - mn0);
        float a1 = __expf(mr1 - mn1);
        mr0 = mn0; mr1 = mn1;

        __syncwarp();   // prior PV reads of Ps done before overwrite
        float sum0 = 0.f, sum1 = 0.f;
#pragma unroll
        for (int nt = 0; nt < 8; nt++) {
            float p00 = __expf(s[nt][0] - mn0);
            float p01 = __expf(s[nt][1] - mn0);
            float p10 = __expf(s[nt][2] - mn1);
            float p11 = __expf(s[nt][3] - mn1);
            sum0 += p00 + p01;
            sum1 += p10 + p11;
            int c = nt * 8 + 2 * t4;
            Ps[(wrow0 + g) * PP + c]     = f2tf(p00);
            Ps[(wrow0 + g) * PP + c + 1] = f2tf(p01);
            Ps[(wrow0 + 8 + g) * PP + c]     = f2tf(p10);
            Ps[(wrow0 + 8 + g) * PP + c + 1] = f2tf(p11);
        }
        sum0 += __shfl_xor_sync(0xffffffffu, sum0, 1);
        sum0 += __shfl_xor_sync(0xffffffffu, sum0, 2);
        sum1 += __shfl_xor_sync(0xffffffffu, sum1, 1);
        sum1 += __shfl_xor_sync(0xffffffffu, sum1, 2);
        l0 = l0 * a0 + sum0;
        l1 = l1 * a1 + sum1;

#pragma unroll
        for (int nt = 0; nt < 8; nt++) {
            o[nt][0] *= a0; o[nt][1] *= a0;
            o[nt][2] *= a1; o[nt][3] *= a1;
        }
        __syncwarp();   // P visible to all lanes of this warp

        // ---- O += P V ----
#pragma unroll
        for (int ks = 0; ks < 8; ks++) {
            const int kc = ks * 8;
            uint32_t af[4];
            af[0] = Ps[(wrow0 + g) * PP + kc + t4];
            af[1] = Ps[(wrow0 + 8 + g) * PP + kc + t4];
            af[2] = Ps[(wrow0 + g) * PP + kc + t4 + 4];
            af[3] = Ps[(wrow0 + 8 + g) * PP + kc + t4 + 4];
#pragma unroll
            for (int nt = 0; nt < 8; nt++) {
                uint32_t b0 = Vs[(kc + t4) * VP + nt * 8 + g];
                uint32_t b1 = Vs[(kc + t4 + 4) * VP + nt * 8 + g];
                mma8(o[nt], af, b0, b1);
            }
        }
    }

    // ---- epilogue: normalize, write ctx (B,S,D) ----
    float inv0 = 1.f / l0, inv1 = 1.f / l1;
    float* out0 = ctx + ((size_t)b * SS + r0g) * DM + h * DH;
    float* out1 = ctx + ((size_t)b * SS + r1g) * DM + h * DH;
#pragma unroll
    for (int nt = 0; nt < 8; nt++) {
        int c = nt * 8 + 2 * t4;
        *(float2*)(out0 + c) = make_float2(o[nt][0] * inv0, o[nt][1] * inv0);
        *(float2*)(out1 + c) = make_float2(o[nt][2] * inv1, o[nt][3] * inv1);
    }
}

// ---------------------------------------------------------------
extern "C" void kernel_launch(void* const* d_in, const int* in_sizes, int n_in,
                              void* d_out, int out_size)
{
    const float* Q  = (const float*)d_in[0];
    const float* K  = (const float*)d_in[1];
    const float* V  = (const float*)d_in[2];
    const uint32_t* mask = (const uint32_t*)d_in[3];
    const float* Wq = (const float*)d_in[4];
    const float* bq = (const float*)d_in[5];
    const float* Wk = (const float*)d_in[6];
    const float* bk = (const float*)d_in[7];
    const float* Wv = (const float*)d_in[8];
    const float* bv = (const float*)d_in[9];
    const float* Wo = (const float*)d_in[10];
    const float* bo = (const float*)d_in[11];
    float* out = (float*)d_out;

    float *qb, *kb, *vb, *ctx;
    cudaGetSymbolAddress((void**)&qb,  g_q);
    cudaGetSymbolAddress((void**)&kb,  g_k);
    cudaGetSymbolAddress((void**)&vb,  g_v);
    cudaGetSymbolAddress((void**)&ctx, g_ctx);

    dim3 gg(DM / 128, (BB * SS) / 128);   // (8, 32)
    dim3 tt(256);

    gemm_tc_kernel<<<gg, tt>>>(Q, Wq, bq, qb, 1);
    gemm_tc_kernel<<<gg, tt>>>(K, Wk, bk, kb, 1);
    gemm_tc_kernel<<<gg, tt>>>(V, Wv, bv, vb, 1);

    const int smem = ATT_SMEM_U32 * (int)sizeof(uint32_t);  // ~108.5 KB
    cudaFuncSetAttribute(attn_tc_kernel, cudaFuncAttributeMaxDynamicSharedMemorySize, smem);
    attn_tc_kernel<<<dim3(SS / QT, HH, BB), tt, smem>>>(qb, kb, vb, mask, ctx);

    gemm_tc_kernel<<<gg, tt>>>(ctx, Wo, bo, out, 0);
}

// round 8
// speedup vs baseline: 2.2824x; 1.0939x over previous
#include <cuda_runtime.h>
#include <cstdint>

#define BB 2
#define SS 2048
#define DM 1024
#define HH 16
#define DH 64
#define NEG_MASK (-9e10f)

__device__ float g_q[BB * HH * SS * DH];
__device__ float g_k[BB * HH * SS * DH];
__device__ float g_v[BB * HH * SS * DH];
__device__ float g_ctx[BB * SS * DM];

__device__ __forceinline__ uint32_t f2tf(float x) {
    uint32_t r;
    asm volatile("cvt.rna.tf32.f32 %0, %1;" : "=r"(r) : "f"(x));
    return r;
}

__device__ __forceinline__ void mma8(float* d, const uint32_t* a, uint32_t b0, uint32_t b1) {
    asm volatile(
        "mma.sync.aligned.m16n8k8.row.col.f32.tf32.tf32.f32 "
        "{%0,%1,%2,%3}, {%4,%5,%6,%7}, {%8,%9}, {%0,%1,%2,%3};\n"
        : "+f"(d[0]), "+f"(d[1]), "+f"(d[2]), "+f"(d[3])
        : "r"(a[0]), "r"(a[1]), "r"(a[2]), "r"(a[3]), "r"(b0), "r"(b1));
}

// ---------------------------------------------------------------
// NT GEMM (tf32, register-prefetch pipelined)
// ---------------------------------------------------------------
#define GBK 32
#define GPAD 36

__global__ __launch_bounds__(256, 1) void gemm_tc_kernel(
    const float* __restrict__ A, const float* __restrict__ W,
    const float* __restrict__ bias, float* __restrict__ C, int split)
{
    __shared__ uint32_t As[128 * GPAD];
    __shared__ uint32_t Ws[128 * GPAD];

    const int tid  = threadIdx.x;
    const int warp = tid >> 5;
    const int lane = tid & 31;
    const int g    = lane >> 2;
    const int t4   = lane & 3;
    const int wm   = warp & 1;
    const int wn   = warp >> 1;
    const int m0   = blockIdx.y * 128;
    const int n0   = blockIdx.x * 128;

    float acc[4][4][4];
#pragma unroll
    for (int mt = 0; mt < 4; mt++)
#pragma unroll
        for (int nt = 0; nt < 4; nt++)
#pragma unroll
            for (int r = 0; r < 4; r++) acc[mt][nt][r] = 0.f;

    const float* Ap = A + (size_t)m0 * DM;
    const float* Wp = W + (size_t)n0 * DM;

    // stage k0 = 0
#pragma unroll
    for (int i = 0; i < 4; i++) {
        int idx = tid + i * 256;
        int r   = idx >> 3;
        int c4  = (idx & 7) * 4;
        float4 a = *(const float4*)(Ap + (size_t)r * DM + c4);
        As[r * GPAD + c4 + 0] = f2tf(a.x); As[r * GPAD + c4 + 1] = f2tf(a.y);
        As[r * GPAD + c4 + 2] = f2tf(a.z); As[r * GPAD + c4 + 3] = f2tf(a.w);
        float4 w = *(const float4*)(Wp + (size_t)r * DM + c4);
        Ws[r * GPAD + c4 + 0] = f2tf(w.x); Ws[r * GPAD + c4 + 1] = f2tf(w.y);
        Ws[r * GPAD + c4 + 2] = f2tf(w.z); Ws[r * GPAD + c4 + 3] = f2tf(w.w);
    }
    __syncthreads();

    float4 pa[4], pw[4];
    for (int k0 = 0; k0 < DM; k0 += GBK) {
        const bool more = (k0 + GBK) < DM;
        if (more) {
#pragma unroll
            for (int i = 0; i < 4; i++) {
                int idx = tid + i * 256;
                int r   = idx >> 3;
                int c4  = (idx & 7) * 4;
                pa[i] = *(const float4*)(Ap + (size_t)r * DM + k0 + GBK + c4);
                pw[i] = *(const float4*)(Wp + (size_t)r * DM + k0 + GBK + c4);
            }
        }

#pragma unroll
        for (int ks = 0; ks < GBK / 8; ks++) {
            const int kc = ks * 8 + t4;
            uint32_t af[4][4];
#pragma unroll
            for (int mt = 0; mt < 4; mt++) {
                int row = wm * 64 + mt * 16 + g;
                af[mt][0] = As[row * GPAD + kc];
                af[mt][1] = As[(row + 8) * GPAD + kc];
                af[mt][2] = As[row * GPAD + kc + 4];
                af[mt][3] = As[(row + 8) * GPAD + kc + 4];
            }
#pragma unroll
            for (int nt = 0; nt < 4; nt++) {
                int col = wn * 32 + nt * 8 + g;
                uint32_t b0 = Ws[col * GPAD + kc];
                uint32_t b1 = Ws[col * GPAD + kc + 4];
#pragma unroll
                for (int mt = 0; mt < 4; mt++)
                    mma8(acc[mt][nt], af[mt], b0, b1);
            }
        }
        __syncthreads();
        if (more) {
#pragma unroll
            for (int i = 0; i < 4; i++) {
                int idx = tid + i * 256;
                int r   = idx >> 3;
                int c4  = (idx & 7) * 4;
                As[r * GPAD + c4 + 0] = f2tf(pa[i].x); As[r * GPAD + c4 + 1] = f2tf(pa[i].y);
                As[r * GPAD + c4 + 2] = f2tf(pa[i].z); As[r * GPAD + c4 + 3] = f2tf(pa[i].w);
                Ws[r * GPAD + c4 + 0] = f2tf(pw[i].x); Ws[r * GPAD + c4 + 1] = f2tf(pw[i].y);
                Ws[r * GPAD + c4 + 2] = f2tf(pw[i].z); Ws[r * GPAD + c4 + 3] = f2tf(pw[i].w);
            }
            __syncthreads();
        }
    }

#pragma unroll
    for (int mt = 0; mt < 4; mt++) {
        int r0 = m0 + wm * 64 + mt * 16 + g;
        int r1 = r0 + 8;
#pragma unroll
        for (int nt = 0; nt < 4; nt++) {
            int c = n0 + wn * 32 + nt * 8 + 2 * t4;
            float2 bi = *(const float2*)(bias + c);
            float v00 = acc[mt][nt][0] + bi.x;
            float v01 = acc[mt][nt][1] + bi.y;
            float v10 = acc[mt][nt][2] + bi.x;
            float v11 = acc[mt][nt][3] + bi.y;
            if (split) {
                int h  = c >> 6;
                int dh = c & 63;
                int b0i = r0 >> 11, s0 = r0 & 2047;
                int b1i = r1 >> 11, s1 = r1 & 2047;
                float* p0 = (float*)C + (((size_t)b0i * HH + h) * SS + s0) * DH + dh;
                float* p1 = (float*)C + (((size_t)b1i * HH + h) * SS + s1) * DH + dh;
                p0[0] = v00; p0[1] = v01;
                p1[0] = v10; p1[1] = v11;
            } else {
                *(float2*)(C + (size_t)r0 * DM + c) = make_float2(v00, v01);
                *(float2*)(C + (size_t)r1 * DM + c) = make_float2(v10, v11);
            }
        }
    }
}

// ---------------------------------------------------------------
// Flash attention, fragment-packed smem + prefetch pipeline.
// 8 warps x 16 q-rows. Layouts:
//  Qp[blk][ks][lane][4]   (LDS.128 A-frag), 8192 u32
//  Kp[ks][t4][n*2+p], stride t4 = 136, ks = 544 (LDS.64 B-frag), 4352 u32
//  Vp same structure, 4352 u32
//  Ps[128][76] (unchanged), 9728 u32
// ---------------------------------------------------------------
#define PP 76
#define KSTR 544
#define TSTR 136
#define ATT_SMEM_U32 (8192 + 4352 + 4352 + 128 * PP)

__global__ __launch_bounds__(256) void attn_tc_kernel(
    const float* __restrict__ q, const float* __restrict__ k,
    const float* __restrict__ v, const uint32_t* __restrict__ mask,
    float* __restrict__ ctx)
{
    extern __shared__ uint32_t su[];
    uint32_t* Qp = su;
    uint32_t* Kp = Qp + 8192;
    uint32_t* Vp = Kp + 4352;
    uint32_t* Ps = Vp + 4352;

    const int tid  = threadIdx.x;
    const int warp = tid >> 5;
    const int lane = tid & 31;
    const int g    = lane >> 2;
    const int t4   = lane & 3;
    const int a7   = lane & 7;
    const int b3   = lane >> 3;      // 0..3
    const int qg0  = blockIdx.x * 128;
    const int h    = blockIdx.y;
    const int b    = blockIdx.z;
    const int wrow0 = warp * 16;

    const float* qptr  = q + (((size_t)b * HH + h) * SS + qg0) * DH;
    const float* kbase = k + (((size_t)b * HH + h) * SS) * DH;
    const float* vbase = v + (((size_t)b * HH + h) * SS) * DH;
    const uint32_t* mbase = mask + (size_t)b * SS * SS;

    // ---- stage Q (packed A-frag layout), scaled ----
#pragma unroll
    for (int i = 0; i < 8; i++) {
        int idx = tid + i * 256;
        int r   = idx >> 4;
        int c0  = (idx & 15) * 4;
        float4 a = *(const float4*)(qptr + (size_t)r * DH + c0);
        int blk = r >> 4, gg = r & 7, half = (r >> 3) & 1;
        int ks  = c0 >> 3, chi = (c0 >> 2) & 1;
        int base = ((blk * 8 + ks) * 32 + 4 * gg) * 4 + (half + 2 * chi);
        Qp[base + 0]  = f2tf(a.x * 0.125f);
        Qp[base + 4]  = f2tf(a.y * 0.125f);
        Qp[base + 8]  = f2tf(a.z * 0.125f);
        Qp[base + 12] = f2tf(a.w * 0.125f);
    }

    // ---- stage K/V chunk 0 ----
    {
        const int n = 8 * warp + a7;
#pragma unroll
        for (int i = 0; i < 4; i++) {
            int c0 = 4 * b3 + 16 * i;
            float4 f  = *(const float4*)(kbase + (size_t)n * DH + c0);
            float4 fv = *(const float4*)(vbase + (size_t)n * DH + c0);
            float ka[4] = {f.x, f.y, f.z, f.w};
            float va[4] = {fv.x, fv.y, fv.z, fv.w};
#pragma unroll
            for (int j = 0; j < 4; j++) {
                int vv = (j + a7) & 3;
                int c  = c0 + vv;
                Kp[(c >> 3) * KSTR + vv * TSTR + n * 2 + ((c >> 2) & 1)] = f2tf(ka[vv]);
                Vp[warp * KSTR + (a7 & 3) * TSTR + c * 2 + (a7 >> 2)]    = f2tf(va[vv]);
            }
        }
    }
    __syncthreads();

    float o[8][4];
#pragma unroll
    for (int nt = 0; nt < 8; nt++)
#pragma unroll
        for (int r = 0; r < 4; r++) o[nt][r] = 0.f;
    float mr0 = -1e30f, mr1 = -1e30f, l0 = 0.f, l1 = 0.f;

    const int r0g = qg0 + wrow0 + g;
    const int r1g = r0g + 8;
    const uint32_t* mrow0p = mbase + (size_t)r0g * SS;
    const uint32_t* mrow1p = mbase + (size_t)r1g * SS;

    float4 kf[4], vf[4];

    for (int kt = 0; kt < SS / 64; kt++) {
        const int kg0 = kt * 64;
        const bool more = (kt + 1) < (SS / 64);

        // prefetch next K/V chunk into regs
        if (more) {
            const int n = 8 * warp + a7;
#pragma unroll
            for (int i = 0; i < 4; i++) {
                int c0 = 4 * b3 + 16 * i;
                kf[i] = *(const float4*)(kbase + (size_t)(kg0 + 64 + n) * DH + c0);
                vf[i] = *(const float4*)(vbase + (size_t)(kg0 + 64 + n) * DH + c0);
            }
        }

        // prefetch masks for this chunk
        uint2 mk0[8], mk1[8];
#pragma unroll
        for (int nt = 0; nt < 8; nt++) {
            int c = kg0 + nt * 8 + 2 * t4;
            mk0[nt] = *(const uint2*)(mrow0p + c);
            mk1[nt] = *(const uint2*)(mrow1p + c);
        }

        // ---- S = Q K^T ----
        float s[8][4];
#pragma unroll
        for (int nt = 0; nt < 8; nt++)
#pragma unroll
            for (int r = 0; r < 4; r++) s[nt][r] = 0.f;

#pragma unroll
        for (int ks = 0; ks < 8; ks++) {
            uint4 aq = *(const uint4*)&Qp[((warp * 8 + ks) * 32 + lane) * 4];
            uint32_t af[4] = {aq.x, aq.y, aq.z, aq.w};
            const uint32_t* kb = &Kp[ks * KSTR + t4 * TSTR + g * 2];
#pragma unroll
            for (int nt = 0; nt < 8; nt++) {
                uint2 bb = *(const uint2*)&kb[nt * 16];
                mma8(s[nt], af, bb.x, bb.y);
            }
        }

        // ---- mask + online softmax ----
        float M0 = -1e30f, M1 = -1e30f;
#pragma unroll
        for (int nt = 0; nt < 8; nt++) {
            if (mk0[nt].x) s[nt][0] += NEG_MASK;
            if (mk0[nt].y) s[nt][1] += NEG_MASK;
            if (mk1[nt].x) s[nt][2] += NEG_MASK;
            if (mk1[nt].y) s[nt][3] += NEG_MASK;
            M0 = fmaxf(M0, fmaxf(s[nt][0], s[nt][1]));
            M1 = fmaxf(M1, fmaxf(s[nt][2], s[nt][3]));
        }
        M0 = fmaxf(M0, __shfl_xor_sync(0xffffffffu, M0, 1));
        M0 = fmaxf(M0, __shfl_xor_sync(0xffffffffu, M0, 2));
        M1 = fmaxf(M1, __shfl_xor_sync(0xffffffffu, M1, 1));
        M1 = fmaxf(M1, __shfl_xor_sync(0xffffffffu, M1, 2));

        float mn0 = fmaxf(mr0, M0);
        float mn1 = fmaxf(mr1, M1);
        float al0 = __expf(mr0 - mn0);
        float al1 = __expf(mr1 - mn1);
        mr0 = mn0; mr1 = mn1;

        __syncwarp();
        float sum0 = 0.f, sum1 = 0.f;
#pragma unroll
        for (int nt = 0; nt < 8; nt++) {
            float p00 = __expf(s[nt][0] - mn0);
            float p01 = __expf(s[nt][1] - mn0);
            float p10 = __expf(s[nt][2] - mn1);
            float p11 = __expf(s[nt][3] - mn1);
            sum0 += p00 + p01;
            sum1 += p10 + p11;
            int c = nt * 8 + 2 * t4;
            Ps[(wrow0 + g) * PP + c]         = f2tf(p00);
            Ps[(wrow0 + g) * PP + c + 1]     = f2tf(p01);
            Ps[(wrow0 + 8 + g) * PP + c]     = f2tf(p10);
            Ps[(wrow0 + 8 + g) * PP + c + 1] = f2tf(p11);
        }
        sum0 += __shfl_xor_sync(0xffffffffu, sum0, 1);
        sum0 += __shfl_xor_sync(0xffffffffu, sum0, 2);
        sum1 += __shfl_xor_sync(0xffffffffu, sum1, 1);
        sum1 += __shfl_xor_sync(0xffffffffu, sum1, 2);
        l0 = l0 * al0 + sum0;
        l1 = l1 * al1 + sum1;

#pragma unroll
        for (int nt = 0; nt < 8; nt++) {
            o[nt][0] *= al0; o[nt][1] *= al0;
            o[nt][2] *= al1; o[nt][3] *= al1;
        }
        __syncwarp();

        // ---- O += P V ----
#pragma unroll
        for (int ks = 0; ks < 8; ks++) {
            const int kc = ks * 8;
            uint32_t af[4];
            af[0] = Ps[(wrow0 + g) * PP + kc + t4];
            af[1] = Ps[(wrow0 + 8 + g) * PP + kc + t4];
            af[2] = Ps[(wrow0 + g) * PP + kc + t4 + 4];
            af[3] = Ps[(wrow0 + 8 + g) * PP + kc + t4 + 4];
            const uint32_t* vb = &Vp[ks * KSTR + t4 * TSTR + g * 2];
#pragma unroll
            for (int nt = 0; nt < 8; nt++) {
                uint2 bv = *(const uint2*)&vb[nt * 16];
                mma8(o[nt], af, bv.x, bv.y);
            }
        }

        __syncthreads();   // all warps done reading Kp/Vp
        if (more) {
            const int n = 8 * warp + a7;
#pragma unroll
            for (int i = 0; i < 4; i++) {
                int c0 = 4 * b3 + 16 * i;
                float ka[4] = {kf[i].x, kf[i].y, kf[i].z, kf[i].w};
                float va[4] = {vf[i].x, vf[i].y, vf[i].z, vf[i].w};
#pragma unroll
                for (int j = 0; j < 4; j++) {
                    int vv = (j + a7) & 3;
                    int c  = c0 + vv;
                    Kp[(c >> 3) * KSTR + vv * TSTR + n * 2 + ((c >> 2) & 1)] = f2tf(ka[vv]);
                    Vp[warp * KSTR + (a7 & 3) * TSTR + c * 2 + (a7 >> 2)]    = f2tf(va[vv]);
                }
            }
            __syncthreads();
        }
    }

    // ---- epilogue ----
    float inv0 = 1.f / l0, inv1 = 1.f / l1;
    float* out0 = ctx + ((size_t)b * SS + r0g) * DM + h * DH;
    float* out1 = ctx + ((size_t)b * SS + r1g) * DM + h * DH;
#pragma unroll
    for (int nt = 0; nt < 8; nt++) {
        int c = nt * 8 + 2 * t4;
        *(float2*)(out0 + c) = make_float2(o[nt][0] * inv0, o[nt][1] * inv0);
        *(float2*)(out1 + c) = make_float2(o[nt][2] * inv1, o[nt][3] * inv1);
    }
}

// ---------------------------------------------------------------
extern "C" void kernel_launch(void* const* d_in, const int* in_sizes, int n_in,
                              void* d_out, int out_size)
{
    const float* Q  = (const float*)d_in[0];
    const float* K  = (const float*)d_in[1];
    const float* V  = (const float*)d_in[2];
    const uint32_t* mask = (const uint32_t*)d_in[3];
    const float* Wq = (const float*)d_in[4];
    const float* bq = (const float*)d_in[5];
    const float* Wk = (const float*)d_in[6];
    const float* bk = (const float*)d_in[7];
    const float* Wv = (const float*)d_in[8];
    const float* bv = (const float*)d_in[9];
    const float* Wo = (const float*)d_in[10];
    const float* bo = (const float*)d_in[11];
    float* out = (float*)d_out;

    float *qb, *kb, *vb, *ctx;
    cudaGetSymbolAddress((void**)&qb,  g_q);
    cudaGetSymbolAddress((void**)&kb,  g_k);
    cudaGetSymbolAddress((void**)&vb,  g_v);
    cudaGetSymbolAddress((void**)&ctx, g_ctx);

    dim3 gg(DM / 128, (BB * SS) / 128);
    dim3 tt(256);

    gemm_tc_kernel<<<gg, tt>>>(Q, Wq, bq, qb, 1);
    gemm_tc_kernel<<<gg, tt>>>(K, Wk, bk, kb, 1);
    gemm_tc_kernel<<<gg, tt>>>(V, Wv, bv, vb, 1);

    const int smem = ATT_SMEM_U32 * (int)sizeof(uint32_t);
    cudaFuncSetAttribute(attn_tc_kernel, cudaFuncAttributeMaxDynamicSharedMemorySize, smem);
    attn_tc_kernel<<<dim3(SS / 128, HH, BB), tt, smem>>>(qb, kb, vb, mask, ctx);

    gemm_tc_kernel<<<gg, tt>>>(ctx, Wo, bo, out, 0);
}